// round 6
// baseline (speedup 1.0000x reference)
#include <cuda_runtime.h>
#include <cuda_bf16.h>
#include <cstdint>

#define N_NODES 100000
#define N_EDGES 1000000
#define DIM 64

// Scratch aggregation buffer (25.6 MB). __device__ global: allowed under alloc guards.
__device__ float g_agg[N_NODES * DIM];
// 1 if edge_index is int64, 0 if int32. Written by detect_kernel every launch.
__device__ int g_idx_is_i64;

// ---------------------------------------------------------------------------
// Kernel 0: detect edge_index dtype.
// If int64 (values < 2^31), every odd 32-bit word (high half) is 0.
// If int32, odd words are random indices in [0, 100000) -> essentially
// impossible for 4096 of them to all be zero.
// ---------------------------------------------------------------------------
__global__ void detect_kernel(const int* __restrict__ ei32) {
    __shared__ int s_nonzero;
    if (threadIdx.x == 0) s_nonzero = 0;
    __syncthreads();
    int found = 0;
    for (int k = threadIdx.x; k < 4096; k += blockDim.x) {
        if (ei32[2 * k + 1] != 0) { found = 1; break; }
    }
    if (found) atomicOr(&s_nonzero, 1);
    __syncthreads();
    if (threadIdx.x == 0) g_idx_is_i64 = (s_nonzero ? 0 : 1);
}

// ---------------------------------------------------------------------------
// Kernel 1: agg = features  (vectorized copy)
// ---------------------------------------------------------------------------
__global__ void init_agg_kernel(const float4* __restrict__ feat4) {
    int i = blockIdx.x * blockDim.x + threadIdx.x;
    if (i < N_NODES * DIM / 4) {
        reinterpret_cast<float4*>(g_agg)[i] = feat4[i];
    }
}

// ---------------------------------------------------------------------------
// Kernel 2: scatter-add messages.
// 16 threads per edge; each thread handles one float4 (4 of the 64 features).
// Uses vectorized red.global.add.v4.f32 (sm_90+) -> 16M RED ops total.
// ---------------------------------------------------------------------------
__global__ void scatter_kernel(const float4* __restrict__ feat4,
                               const void* __restrict__ edge_index,
                               const float* __restrict__ edge_weight) {
    long long t = (long long)blockIdx.x * blockDim.x + threadIdx.x;
    if (t >= (long long)N_EDGES * 16) return;
    int e = (int)(t >> 4);
    int q = (int)(t & 15);

    long long src, dst;
    if (g_idx_is_i64) {
        const long long* ei = (const long long*)edge_index;
        src = ei[e];
        dst = ei[N_EDGES + e];
    } else {
        const int* ei = (const int*)edge_index;
        src = ei[e];
        dst = ei[N_EDGES + e];
    }
    // Bounds guard: a wrong dtype/binding theory becomes rel_err, not a crash.
    if (src < 0 || src >= N_NODES || dst < 0 || dst >= N_NODES) return;

    float w = edge_weight[e];

    float4 v = feat4[src * 16 + q];
    v.x *= w; v.y *= w; v.z *= w; v.w *= w;

    float* p = &g_agg[dst * DIM + q * 4];
    asm volatile("red.global.add.v4.f32 [%0], {%1, %2, %3, %4};"
                 :: "l"(p), "f"(v.x), "f"(v.y), "f"(v.z), "f"(v.w)
                 : "memory");
}

// ---------------------------------------------------------------------------
// Kernel 3: out = agg @ W^T + b
// Block = 256 threads processes 128 rows. W (64x64) and the 128-row A tile are
// staged in smem (padded stride 68 floats to rotate banks). Each thread owns a
// 2-row x 16-col register tile; inner loop is float4 LDS + scalar FFMA.
// ---------------------------------------------------------------------------
__global__ void gemm_kernel(const float* __restrict__ W,
                            const float* __restrict__ b,
                            float* __restrict__ out) {
    __shared__ float Ws[64][68];    // W[o][k], padded
    __shared__ float As[128][68];   // agg rows, padded
    __shared__ float bs[64];

    int tid = threadIdx.x;          // 256 threads
    int row0 = blockIdx.x * 128;

    // Load W: 1024 float4, 4 per thread
    for (int i = tid; i < 1024; i += 256) {
        int o  = i >> 4;
        int k4 = i & 15;
        float4 w = reinterpret_cast<const float4*>(W)[o * 16 + k4];
        *reinterpret_cast<float4*>(&Ws[o][k4 * 4]) = w;
    }
    if (tid < 64) bs[tid] = b[tid];

    // Load A tile: 128 rows x 16 float4 = 2048 float4, 8 per thread
    for (int i = tid; i < 2048; i += 256) {
        int r  = i >> 4;
        int k4 = i & 15;
        int gr = row0 + r;
        float4 v = make_float4(0.f, 0.f, 0.f, 0.f);
        if (gr < N_NODES) {
            v = reinterpret_cast<const float4*>(g_agg)[gr * 16 + k4];
        }
        *reinterpret_cast<float4*>(&As[r][k4 * 4]) = v;
    }
    __syncthreads();

    int tx = tid & 3;        // output group: 16 outputs
    int ty = tid >> 2;       // row group: 2 rows
    int r0 = ty * 2;
    int o0 = tx * 16;

    float acc0[16], acc1[16];
#pragma unroll
    for (int j = 0; j < 16; j++) {
        acc0[j] = bs[o0 + j];
        acc1[j] = bs[o0 + j];
    }

#pragma unroll
    for (int k4 = 0; k4 < 16; k4++) {
        float4 a0 = *reinterpret_cast<const float4*>(&As[r0][k4 * 4]);
        float4 a1 = *reinterpret_cast<const float4*>(&As[r0 + 1][k4 * 4]);
#pragma unroll
        for (int j = 0; j < 16; j++) {
            float4 w = *reinterpret_cast<const float4*>(&Ws[o0 + j][k4 * 4]);
            acc0[j] += a0.x * w.x + a0.y * w.y + a0.z * w.z + a0.w * w.w;
            acc1[j] += a1.x * w.x + a1.y * w.y + a1.z * w.z + a1.w * w.w;
        }
    }

    // Store 2 rows x 16 outputs
#pragma unroll
    for (int i = 0; i < 2; i++) {
        int gr = row0 + r0 + i;
        if (gr < N_NODES) {
            float* accp = (i == 0) ? acc0 : acc1;
#pragma unroll
            for (int j4 = 0; j4 < 4; j4++) {
                float4 v = make_float4(accp[j4 * 4 + 0], accp[j4 * 4 + 1],
                                       accp[j4 * 4 + 2], accp[j4 * 4 + 3]);
                reinterpret_cast<float4*>(out)[(long long)gr * 16 + (o0 >> 2) + j4] = v;
            }
        }
    }
}

// ---------------------------------------------------------------------------
// Launch. Inputs bound by element count (primary) with byte-count and
// positional fallbacks:
//   features    : 6,400,000 elems (float32)     [25,600,000 B]
//   edge_index  : 2,000,000 elems (int64/int32) [16,000,000 or 8,000,000 B]
//   edge_weight : 1,000,000 elems (float32)     [ 4,000,000 B]
//   W           :     4,096 elems (float32)     [    16,384 B]
//   b           :        64 elems (float32)     [       256 B]
// ---------------------------------------------------------------------------
extern "C" void kernel_launch(void* const* d_in, const int* in_sizes, int n_in,
                              void* d_out, int out_size) {
    const float4* feat4 = nullptr;
    const void*   ei    = nullptr;
    const float*  ew    = nullptr;
    const float*  W     = nullptr;
    const float*  b     = nullptr;

    for (int i = 0; i < n_in; i++) {
        switch (in_sizes[i]) {
            case 6400000: case 25600000:               feat4 = (const float4*)d_in[i]; break;
            case 2000000: case 16000000: case 8000000: ei    = d_in[i];                break;
            case 1000000: case 4000000:                ew    = (const float*)d_in[i];  break;
            case 4096:    case 16384:                  W     = (const float*)d_in[i];  break;
            case 64:      case 256:                    b     = (const float*)d_in[i];  break;
            default: break;
        }
    }
    // Positional fallback (metadata dict order) if size matching failed.
    if ((!feat4 || !ei || !ew || !W || !b) && n_in >= 5) {
        feat4 = (const float4*)d_in[0];
        ei    = d_in[1];
        ew    = (const float*)d_in[2];
        W     = (const float*)d_in[3];
        b     = (const float*)d_in[4];
    }

    float* out = (float*)d_out;

    // 0) detect edge_index dtype (int32 vs int64)
    detect_kernel<<<1, 256>>>((const int*)ei);
    // 1) agg = features
    {
        int n = N_NODES * DIM / 4;           // 1.6M float4
        init_agg_kernel<<<(n + 255) / 256, 256>>>(feat4);
    }
    // 2) scatter-add
    {
        long long n = (long long)N_EDGES * 16;   // 16M threads
        int blocks = (int)((n + 255) / 256);
        scatter_kernel<<<blocks, 256>>>(feat4, ei, ew);
    }
    // 3) GEMM + bias
    {
        int blocks = (N_NODES + 127) / 128;      // 782
        gemm_kernel<<<blocks, 256>>>(W, b, out);
    }
}

// round 12
// speedup vs baseline: 1.6269x; 1.6269x over previous
#include <cuda_runtime.h>
#include <cuda_bf16.h>
#include <cstdint>

#define N_NODES 100000
#define N_EDGES 1000000
#define DIM 64

typedef unsigned long long ull;

// Scratch aggregation buffer (25.6 MB). __device__ global: allowed under alloc guards.
__device__ float g_agg[N_NODES * DIM];
// 1 if edge_index is int64, 0 if int32. Written by detect_kernel every launch.
__device__ int g_idx_is_i64;

// ---------------------------------------------------------------------------
// Kernel 0: detect edge_index dtype (int32 vs int64) — proven working.
// ---------------------------------------------------------------------------
__global__ void detect_kernel(const int* __restrict__ ei32) {
    __shared__ int s_nonzero;
    if (threadIdx.x == 0) s_nonzero = 0;
    __syncthreads();
    int found = 0;
    for (int k = threadIdx.x; k < 4096; k += blockDim.x) {
        if (ei32[2 * k + 1] != 0) { found = 1; break; }
    }
    if (found) atomicOr(&s_nonzero, 1);
    __syncthreads();
    if (threadIdx.x == 0) g_idx_is_i64 = (s_nonzero ? 0 : 1);
}

// ---------------------------------------------------------------------------
// Kernel 1: agg = features  (vectorized copy)
// ---------------------------------------------------------------------------
__global__ void init_agg_kernel(const float4* __restrict__ feat4) {
    int i = blockIdx.x * blockDim.x + threadIdx.x;
    if (i < N_NODES * DIM / 4) {
        reinterpret_cast<float4*>(g_agg)[i] = feat4[i];
    }
}

// ---------------------------------------------------------------------------
// Kernel 2: scatter-add via red.global.add.v4.f32 (unchanged; ~L2-BW bound)
// ---------------------------------------------------------------------------
__global__ void scatter_kernel(const float4* __restrict__ feat4,
                               const void* __restrict__ edge_index,
                               const float* __restrict__ edge_weight) {
    long long t = (long long)blockIdx.x * blockDim.x + threadIdx.x;
    if (t >= (long long)N_EDGES * 16) return;
    int e = (int)(t >> 4);
    int q = (int)(t & 15);

    long long src, dst;
    if (g_idx_is_i64) {
        const long long* ei = (const long long*)edge_index;
        src = ei[e];
        dst = ei[N_EDGES + e];
    } else {
        const int* ei = (const int*)edge_index;
        src = ei[e];
        dst = ei[N_EDGES + e];
    }
    if (src < 0 || src >= N_NODES || dst < 0 || dst >= N_NODES) return;

    float w = edge_weight[e];
    float4 v = feat4[src * 16 + q];
    v.x *= w; v.y *= w; v.z *= w; v.w *= w;

    float* p = &g_agg[dst * DIM + q * 4];
    asm volatile("red.global.add.v4.f32 [%0], {%1, %2, %3, %4};"
                 :: "l"(p), "f"(v.x), "f"(v.y), "f"(v.z), "f"(v.w)
                 : "memory");
}

// ---------------------------------------------------------------------------
// Kernel 3: out = agg @ W^T + b
// Block: 256 threads -> 256 rows x 64 cols. Thread tile: 8 rows x 8 cols.
// Wt[k][o] transposed in smem, stride 66 + group-shift -> conflict-free LDS.64
// of column PAIRS feeding packed fma.rn.f32x2 (full-rate fp32 on sm_103a).
// A tile swizzled per row-group (k4 ^ rg) -> conflict-free LDS.128 across the
// 4 row-groups of a warp.
// ---------------------------------------------------------------------------
#define WT_STRIDE 66
#define A_STRIDE  68
#define WT_WORDS  (64 * WT_STRIDE)              // 4224 floats
#define A_WORDS   (256 * A_STRIDE)              // 17408 floats
#define GEMM_SMEM ((WT_WORDS + A_WORDS) * 4)    // 86528 bytes

__device__ __forceinline__ int windex(int o) { return o + ((o >> 5) << 1); }

__device__ __forceinline__ ull f32x2_dup(float x) {
    ull r;
    asm("mov.b64 %0, {%1, %1};" : "=l"(r) : "f"(x));
    return r;
}
__device__ __forceinline__ ull f32x2_fma(ull a, ull b, ull c) {
    ull d;
    asm("fma.rn.f32x2 %0, %1, %2, %3;" : "=l"(d) : "l"(a), "l"(b), "l"(c));
    return d;
}

__global__ __launch_bounds__(256, 2)
void gemm_kernel(const float* __restrict__ W,
                 const float* __restrict__ b,
                 float* __restrict__ out) {
    extern __shared__ float smem[];
    float* Wt = smem;               // [64][WT_STRIDE] with windex column shift
    float* As = smem + WT_WORDS;    // [256][A_STRIDE] with k4^rg swizzle

    const int tid  = threadIdx.x;
    const int row0 = blockIdx.x * 256;

    // Stage W transposed: Wt[k][windex(o)] = W[o][k]
    for (int t = tid; t < 4096; t += 256) {
        int o = t >> 6;
        int k = t & 63;
        Wt[k * WT_STRIDE + windex(o)] = W[t];
    }

    // Stage A tile (swizzled), zero-padded past N_NODES
    for (int t = tid; t < 4096; t += 256) {
        int r  = t >> 4;
        int k4 = t & 15;
        int gr = row0 + r;
        float4 v = make_float4(0.f, 0.f, 0.f, 0.f);
        if (gr < N_NODES) {
            v = reinterpret_cast<const float4*>(g_agg)[(long long)gr * 16 + k4];
        }
        int sw = (k4 ^ ((r >> 3) & 3)) * 4;
        *reinterpret_cast<float4*>(&As[r * A_STRIDE + sw]) = v;
    }
    __syncthreads();

    const int cg = tid & 7;          // column group: cols o0..o0+7
    const int rg = tid >> 3;         // row group:    rows r0..r0+7
    const int o0 = cg * 8;
    const int r0 = rg * 8;
    const int rsw = rg & 3;          // row-group swizzle key

    // acc2[i*4+j2] = packed (acc[row i][col o0+2j2], acc[row i][col o0+2j2+1])
    ull acc2[32];
    {
        ull b2[4];
#pragma unroll
        for (int j2 = 0; j2 < 4; j2++) {
            float2 bv = *reinterpret_cast<const float2*>(&b[o0 + 2 * j2]);
            ull r;
            asm("mov.b64 %0, {%1, %2};" : "=l"(r) : "f"(bv.x), "f"(bv.y));
            b2[j2] = r;
        }
#pragma unroll
        for (int i = 0; i < 8; i++)
#pragma unroll
            for (int j2 = 0; j2 < 4; j2++)
                acc2[i * 4 + j2] = b2[j2];
    }

    const int wbase = windex(o0);    // windex is linear within an aligned 8-col group

#pragma unroll 1
    for (int k4 = 0; k4 < 16; k4++) {
        // W pairs for 4 k-values x 4 col-pairs (conflict-free LDS.64)
        ull w2[16];
#pragma unroll
        for (int k = 0; k < 4; k++) {
            const float* wrow = &Wt[(k4 * 4 + k) * WT_STRIDE + wbase];
#pragma unroll
            for (int j2 = 0; j2 < 4; j2++)
                w2[k * 4 + j2] = *reinterpret_cast<const ull*>(&wrow[2 * j2]);
        }

        const int sw = (k4 ^ rsw) * 4;
#pragma unroll
        for (int i = 0; i < 8; i++) {
            float4 a = *reinterpret_cast<const float4*>(&As[(r0 + i) * A_STRIDE + sw]);
            ull ax = f32x2_dup(a.x);
            ull ay = f32x2_dup(a.y);
            ull az = f32x2_dup(a.z);
            ull aw = f32x2_dup(a.w);
#pragma unroll
            for (int j2 = 0; j2 < 4; j2++) {
                ull v = acc2[i * 4 + j2];
                v = f32x2_fma(ax, w2[0 * 4 + j2], v);
                v = f32x2_fma(ay, w2[1 * 4 + j2], v);
                v = f32x2_fma(az, w2[2 * 4 + j2], v);
                v = f32x2_fma(aw, w2[3 * 4 + j2], v);
                acc2[i * 4 + j2] = v;
            }
        }
    }

    // Store: 8 floats per row = 2 float4 (acc2 pairs are contiguous cols)
#pragma unroll
    for (int i = 0; i < 8; i++) {
        int gr = row0 + r0 + i;
        if (gr < N_NODES) {
            float2 p0, p1, p2, p3;
            asm("mov.b64 {%0, %1}, %2;" : "=f"(p0.x), "=f"(p0.y) : "l"(acc2[i * 4 + 0]));
            asm("mov.b64 {%0, %1}, %2;" : "=f"(p1.x), "=f"(p1.y) : "l"(acc2[i * 4 + 1]));
            asm("mov.b64 {%0, %1}, %2;" : "=f"(p2.x), "=f"(p2.y) : "l"(acc2[i * 4 + 2]));
            asm("mov.b64 {%0, %1}, %2;" : "=f"(p3.x), "=f"(p3.y) : "l"(acc2[i * 4 + 3]));
            float4 v0 = make_float4(p0.x, p0.y, p1.x, p1.y);
            float4 v1 = make_float4(p2.x, p2.y, p3.x, p3.y);
            float4* op = &reinterpret_cast<float4*>(out)[(long long)gr * 16 + cg * 2];
            op[0] = v0;
            op[1] = v1;
        }
    }
}

// ---------------------------------------------------------------------------
// Launch. Inputs bound by element count (primary) with byte-count and
// positional fallbacks (proven working).
// ---------------------------------------------------------------------------
extern "C" void kernel_launch(void* const* d_in, const int* in_sizes, int n_in,
                              void* d_out, int out_size) {
    const float4* feat4 = nullptr;
    const void*   ei    = nullptr;
    const float*  ew    = nullptr;
    const float*  W     = nullptr;
    const float*  b     = nullptr;

    for (int i = 0; i < n_in; i++) {
        switch (in_sizes[i]) {
            case 6400000: case 25600000:               feat4 = (const float4*)d_in[i]; break;
            case 2000000: case 16000000: case 8000000: ei    = d_in[i];                break;
            case 1000000: case 4000000:                ew    = (const float*)d_in[i];  break;
            case 4096:    case 16384:                  W     = (const float*)d_in[i];  break;
            case 64:      case 256:                    b     = (const float*)d_in[i];  break;
            default: break;
        }
    }
    if ((!feat4 || !ei || !ew || !W || !b) && n_in >= 5) {
        feat4 = (const float4*)d_in[0];
        ei    = d_in[1];
        ew    = (const float*)d_in[2];
        W     = (const float*)d_in[3];
        b     = (const float*)d_in[4];
    }

    float* out = (float*)d_out;

    // Idempotent, capture-safe, no static state (per the stub's rules).
    cudaFuncSetAttribute(gemm_kernel,
                         cudaFuncAttributeMaxDynamicSharedMemorySize, GEMM_SMEM);

    // 0) detect edge_index dtype
    detect_kernel<<<1, 256>>>((const int*)ei);
    // 1) agg = features
    {
        int n = N_NODES * DIM / 4;
        init_agg_kernel<<<(n + 255) / 256, 256>>>(feat4);
    }
    // 2) scatter-add
    {
        long long n = (long long)N_EDGES * 16;
        int blocks = (int)((n + 255) / 256);
        scatter_kernel<<<blocks, 256>>>(feat4, ei, ew);
    }
    // 3) GEMM + bias (256 rows per block)
    {
        int blocks = (N_NODES + 255) / 256;      // 391
        gemm_kernel<<<blocks, 256, GEMM_SMEM>>>(W, b, out);
    }
}